// round 1
// baseline (speedup 1.0000x reference)
#include <cuda_runtime.h>
#include <cuda_bf16.h>

#define BB   32
#define CC   512
#define HH   56
#define WW   56
#define HW   3136            // 56*56
#define BC   (BB*CC)         // 16384
#define BHW  (BB*HW)         // 100352
#define TPAD 57              // padded smem row stride (floats)

__device__ float    g_keep[BC];
__device__ unsigned g_xmax[BC];   // float bits, values >= 0
__device__ float    g_psum[BC];
__device__ float    g_thres[BC];
__device__ float    g_bb[BHW];

// ---------------------------------------------------------------------------
// K1: per-(b,c) spatial sum/max of relu(x) -> keep mask; also zero-init accums
// ---------------------------------------------------------------------------
__global__ void k1_stats(const float* __restrict__ x) {
    int bc = blockIdx.x;
    const float4* row = (const float4*)(x + (size_t)bc * HW);
    float s = 0.f, m = 0.f;
    for (int i = threadIdx.x; i < HW / 4; i += blockDim.x) {
        float4 v = row[i];
        float a = fmaxf(v.x, 0.f), b = fmaxf(v.y, 0.f);
        float c = fmaxf(v.z, 0.f), d = fmaxf(v.w, 0.f);
        s += (a + b) + (c + d);
        m = fmaxf(m, fmaxf(fmaxf(a, b), fmaxf(c, d)));
    }
    __shared__ float ss[8], sm[8];
    #pragma unroll
    for (int o = 16; o; o >>= 1) {
        s += __shfl_down_sync(0xFFFFFFFFu, s, o);
        m  = fmaxf(m, __shfl_down_sync(0xFFFFFFFFu, m, o));
    }
    int wid = threadIdx.x >> 5, lid = threadIdx.x & 31;
    if (lid == 0) { ss[wid] = s; sm[wid] = m; }
    __syncthreads();
    if (threadIdx.x == 0) {
        float S = 0.f, M = 0.f;
        #pragma unroll
        for (int i = 0; i < 8; i++) { S += ss[i]; M = fmaxf(M, sm[i]); }
        float avg = S * (1.0f / HW);
        g_keep[bc] = ((M - avg) < 0.5f) ? 0.f : 1.f;
        g_xmax[bc] = 0u;
        g_psum[bc] = 0.f;
    }
}

// ---------------------------------------------------------------------------
// K2: fused stage2+stage3. One block per (b,h) row-slab: 512ch x 56w in SMEM.
//   phase A: load masked relu(x) slab (float4, coalesced)
//   phase B: per-w channel max/mean  -> bb[w]  (store to gmem for K4)
//   phase C: per-c max/sum over w of bb*v -> atomic merge into g_xmax/g_psum
// ---------------------------------------------------------------------------
extern __shared__ float stile[];   // CC * TPAD floats = 116736 B

__global__ void __launch_bounds__(224, 1) k2_bb(const float* __restrict__ x) {
    int h = blockIdx.x, b = blockIdx.y;
    const float* xb = x + ((size_t)b * CC) * HW + (size_t)h * WW;
    __shared__ float pmax[4][WW], psum2[4][WW], sbb[WW];

    // phase A: load
    for (int idx = threadIdx.x; idx < CC * (WW / 4); idx += 224) {
        int c = idx / (WW / 4), w4 = idx % (WW / 4);
        float4 v = *(const float4*)(xb + (size_t)c * HW + w4 * 4);
        float k = g_keep[b * CC + c];
        float* d = &stile[c * TPAD + w4 * 4];
        d[0] = k * fmaxf(v.x, 0.f);
        d[1] = k * fmaxf(v.y, 0.f);
        d[2] = k * fmaxf(v.z, 0.f);
        d[3] = k * fmaxf(v.w, 0.f);
    }
    __syncthreads();

    // phase B1: partial channel reduce (4 groups of 128 channels per w)
    {
        int g = threadIdx.x / WW, w = threadIdx.x % WW;   // g in 0..3
        float mx = 0.f, sm = 0.f;
        int c0 = g * (CC / 4);
        #pragma unroll 8
        for (int c = c0; c < c0 + CC / 4; c++) {
            float v = stile[c * TPAD + w];
            mx = fmaxf(mx, v); sm += v;
        }
        pmax[g][w] = mx; psum2[g][w] = sm;
    }
    __syncthreads();

    // phase B2: finalize bb per w
    if (threadIdx.x < WW) {
        int w = threadIdx.x;
        float mx = fmaxf(fmaxf(pmax[0][w], pmax[1][w]), fmaxf(pmax[2][w], pmax[3][w]));
        float sm = (psum2[0][w] + psum2[1][w]) + (psum2[2][w] + psum2[3][w]);
        float bb = 1.f - expf(-(mx - sm * (1.0f / CC)));   // cmax >= cmean
        sbb[w] = bb;
        g_bb[b * HW + h * WW + w] = bb;
    }
    __syncthreads();

    // phase C: per-c spatial-row reduce of x2 = bb * v, merge globally
    for (int c = threadIdx.x; c < CC; c += 224) {
        float mx = 0.f, sm = 0.f;
        const float* row = &stile[c * TPAD];
        #pragma unroll
        for (int w = 0; w < WW; w++) {
            float v = sbb[w] * row[w];
            mx = fmaxf(mx, v); sm += v;
        }
        atomicMax(&g_xmax[b * CC + c], __float_as_uint(mx));
        atomicAdd(&g_psum[b * CC + c], sm);
    }
}

// ---------------------------------------------------------------------------
// K3: tiny FC gates (pooled @ W1^T, pooled @ W3^T) -> thres per (b,c)
// ---------------------------------------------------------------------------
__global__ void k3_gates(const float* __restrict__ W1, const float* __restrict__ W3) {
    int b = blockIdx.x;
    __shared__ float pooled[CC];
    int c = threadIdx.x;
    pooled[c] = g_psum[b * CC + c] * (1.0f / HW);
    __syncthreads();
    float d1 = 0.f, d3 = 0.f;
    const float* w1r = W1 + (size_t)c * CC;
    const float* w3r = W3 + (size_t)c * CC;
    #pragma unroll 8
    for (int k = 0; k < CC; k++) {
        float p = pooled[k];
        d1 = fmaf(p, w1r[k], d1);
        d3 = fmaf(p, w3r[k], d3);
    }
    float c1 = 1.f / (1.f + expf(-d1));
    float r3 = fmaxf(d3, 0.f);
    float c3 = (r3 < 1.0f) ? 1.2f : r3;
    g_thres[b * CC + c] = c1 * c3 * __uint_as_float(g_xmax[b * CC + c]);
}

// ---------------------------------------------------------------------------
// K4: final thresholding. Recompute x2 = bb*(keep*relu(x)); bb/keep/thres hit L2.
// ---------------------------------------------------------------------------
__global__ void k4_final(const float* __restrict__ x, float* __restrict__ out) {
    unsigned v = blockIdx.x * blockDim.x + threadIdx.x;
    unsigned e = v * 4u;
    if (e >= (unsigned)BB * CC * HW) return;
    unsigned bc  = e / HW;
    unsigned pos = e % HW;          // 4-aligned; stays within one (h,w) row set
    unsigned b   = bc >> 9;
    float keep = g_keep[bc];
    float th   = g_thres[bc];
    const float* bbp = &g_bb[b * HW + pos];
    float4 xv = *(const float4*)(x + e);
    float4 o;
    float t;
    t = bbp[0] * (keep * fmaxf(xv.x, 0.f)); o.x = (t < th) ? 0.f : t;
    t = bbp[1] * (keep * fmaxf(xv.y, 0.f)); o.y = (t < th) ? 0.f : t;
    t = bbp[2] * (keep * fmaxf(xv.z, 0.f)); o.z = (t < th) ? 0.f : t;
    t = bbp[3] * (keep * fmaxf(xv.w, 0.f)); o.w = (t < th) ? 0.f : t;
    *(float4*)(out + e) = o;
}

// ---------------------------------------------------------------------------
extern "C" void kernel_launch(void* const* d_in, const int* in_sizes, int n_in,
                              void* d_out, int out_size) {
    const float* x  = (const float*)d_in[0];
    const float* W1 = (const float*)d_in[1];
    const float* W3 = (const float*)d_in[2];
    float* out = (float*)d_out;

    static const int k2_smem = CC * TPAD * sizeof(float);   // 116736 B
    cudaFuncSetAttribute(k2_bb, cudaFuncAttributeMaxDynamicSharedMemorySize, k2_smem);

    k1_stats<<<BC, 256>>>(x);
    k2_bb<<<dim3(HH, BB), 224, k2_smem>>>(x);
    k3_gates<<<BB, CC>>>(W1, W3);

    unsigned nvec = (unsigned)BB * CC * HW / 4u;            // 12,845,056
    k4_final<<<(nvec + 255) / 256, 256>>>(x, out);
}